// round 9
// baseline (speedup 1.0000x reference)
#include <cuda_runtime.h>
#include <cuda_fp16.h>

#define NN 100000
#define NE 2500000
#define NG 1000
#define HD 32
#define SCAN_B 512
#define NB ((NN + SCAN_B - 1) / SCAN_B)   // 196

// ---- scratch (__device__ globals; allocation-free) ----
// Never passed as kernel args from host; referenced directly in device code.
__device__ int   g_is64;                          // 1 if index inputs are int64
__device__ __align__(16) float  g_deg[NN];        // dinv (written by k_prep)
__device__ __align__(16) int    g_cnt[NN];        // in-degree histogram
__device__ __align__(16) int    g_scani[NN];      // per-block inclusive scan
__device__ __align__(16) int    g_bsum[256];      // block totals
__device__ __align__(16) int    g_bscan[256];     // scanned block totals
__device__ __align__(16) int    g_off[NN];        // CSR start offsets
__device__ __align__(16) int    g_cur[NN];        // fill cursors
__device__ __align__(16) int2   g_csr[NE];        // packed {src, __float_as_int(ew)}
__device__ __align__(16) float4 g_x[NN];          // dinv[i] * x[i]  (prescaled input)
__device__ __align__(16) __half g_Ah[NN * HD];    // fp16 prescaled feature matrices
__device__ __align__(16) __half g_Bh[NN * HD];
__device__ __align__(16) float  g_gsum[NG * HD];
__device__ __align__(16) float  g_gcnt[NG];

__device__ __forceinline__ int ldidx(const void* p, long long e) {
    if (g_is64) return (int)((const long long*)p)[e];
    return ((const int*)p)[e];
}

// init + index-width detection (thread 0).
// int64 values < 2^31 have all-zero high words -> odd int32 words all zero.
__global__ void k_init(const void* ei) {
    int t = blockIdx.x * blockDim.x + threadIdx.x;
    if (t == 0) {
        const int* p = (const int*)ei;
        int z = 0;
#pragma unroll
        for (int j = 1; j < 64; j += 2) z |= p[j];
        g_is64 = (z == 0) ? 1 : 0;
    }
    if (t < NN) g_cnt[t] = 0;
    if (t < NG * HD) g_gsum[t] = 0.f;
    if (t < NG) g_gcnt[t] = 0.f;
}

// histogram only: single int atomic per edge, reads only the col half
__global__ void k_hist(const void* __restrict__ ei) {
    int e = blockIdx.x * blockDim.x + threadIdx.x;
    if (e >= NE) return;
    int c = ldidx(ei, (long long)NE + e);
    atomicAdd(&g_cnt[c], 1);
}

// ---- 3-stage exclusive prefix scan of g_cnt -> g_off ----
__global__ void k_scan1() {
    __shared__ int s[SCAN_B];
    int tid = threadIdx.x;
    int i = blockIdx.x * SCAN_B + tid;
    s[tid] = (i < NN) ? g_cnt[i] : 0;
    __syncthreads();
#pragma unroll
    for (int off = 1; off < SCAN_B; off <<= 1) {
        int v = (tid >= off) ? s[tid - off] : 0;
        __syncthreads();
        s[tid] += v;
        __syncthreads();
    }
    if (i < NN) g_scani[i] = s[tid];
    if (tid == SCAN_B - 1) g_bsum[blockIdx.x] = s[tid];
}

__global__ void k_scan2() {
    __shared__ int s[256];
    int tid = threadIdx.x;
    s[tid] = (tid < NB) ? g_bsum[tid] : 0;
    __syncthreads();
#pragma unroll
    for (int off = 1; off < 256; off <<= 1) {
        int v = (tid >= off) ? s[tid - off] : 0;
        __syncthreads();
        s[tid] += v;
        __syncthreads();
    }
    g_bscan[tid] = s[tid];
}

__global__ void k_scan3() {
    int i = blockIdx.x * blockDim.x + threadIdx.x;
    if (i >= NN) return;
    int b = i / SCAN_B;
    int add = (b > 0) ? g_bscan[b - 1] : 0;
    int excl = add + g_scani[i] - g_cnt[i];
    g_off[i] = excl;
    g_cur[i] = excl;
}

// CSR fill: store {src, raw ew} -- no dinv dependency, no random reads
__global__ void k_fill(const void* __restrict__ ei, const float* __restrict__ ew) {
    int e = blockIdx.x * blockDim.x + threadIdx.x;
    if (e >= NE) return;
    int r = ldidx(ei, e);
    int c = ldidx(ei, (long long)NE + e);
    int p = atomicAdd(&g_cur[c], 1);
    g_csr[p] = make_int2(r, __float_as_int(ew[e]));
}

// prep (warp per node): deg = sum of ew over the node's CSR bucket (coalesced,
// atomic-free), dinv = rsqrt(deg+1); prescale x: g_x[i] = dinv * x[i].
__global__ void k_prep(const float* __restrict__ x) {
    int t = blockIdx.x * blockDim.x + threadIdx.x;
    int i = t >> 5, lane = t & 31;
    if (i >= NN) return;
    int beg = g_off[i];
    int cnt = g_cnt[i];
    float s = 0.f;
    for (int e = lane; e < cnt; e += 32)
        s += __int_as_float(g_csr[beg + e].y);
#pragma unroll
    for (int d = 1; d < 32; d <<= 1)
        s += __shfl_xor_sync(0xffffffffu, s, d);
    float dv = rsqrtf(s + 1.0f);   // +1 = self-loop weight
    if (lane == 0) {
        g_deg[i] = dv;
        float4 xi = __ldg(&reinterpret_cast<const float4*>(x)[i]);
        g_x[i] = make_float4(dv * xi.x, dv * xi.y, dv * xi.z, dv * xi.w);
    }
}

// Layer 1 (prescaled input): agg = dv*(sum_e ew*g_x[src] + g_x[i]);
// h1 = relu(agg@W1 + b1); store g_Bh[i] = fp16(dv * (h1@W2)).
__global__ void k_layer1(const float* __restrict__ W1, const float* __restrict__ b1,
                         const float* __restrict__ W2) {
    __shared__ float W1s[4 * HD];
    __shared__ float W2s[HD * HD];
    int tid = threadIdx.x;
    for (int k = tid; k < 4 * HD; k += blockDim.x)  W1s[k] = W1[k];
    for (int k = tid; k < HD * HD; k += blockDim.x) W2s[k] = W2[k];
    __syncthreads();
    int t = blockIdx.x * blockDim.x + tid;
    int i = t >> 5, lane = t & 31;
    if (i >= NN) return;

    int beg = g_off[i];
    int cnt = g_cnt[i];
    float4 acc = make_float4(0.f, 0.f, 0.f, 0.f);
    for (int e = lane; e < cnt; e += 32) {
        int2 ce = g_csr[beg + e];
        float w = __int_as_float(ce.y);
        float4 xv = g_x[ce.x];
        acc.x = fmaf(w, xv.x, acc.x);
        acc.y = fmaf(w, xv.y, acc.y);
        acc.z = fmaf(w, xv.z, acc.z);
        acc.w = fmaf(w, xv.w, acc.w);
    }
#pragma unroll
    for (int d = 1; d < 32; d <<= 1) {
        acc.x += __shfl_xor_sync(0xffffffffu, acc.x, d);
        acc.y += __shfl_xor_sync(0xffffffffu, acc.y, d);
        acc.z += __shfl_xor_sync(0xffffffffu, acc.z, d);
        acc.w += __shfl_xor_sync(0xffffffffu, acc.w, d);
    }
    float4 xi = g_x[i];
    float dv = g_deg[i];
    acc.x = (acc.x + xi.x) * dv;
    acc.y = (acc.y + xi.y) * dv;
    acc.z = (acc.z + xi.z) * dv;
    acc.w = (acc.w + xi.w) * dv;

    // h1[lane] = relu(agg4 . W1[:,lane] + b1[lane])
    float h = __ldg(&b1[lane]);
    h = fmaf(acc.x, W1s[0 * HD + lane], h);
    h = fmaf(acc.y, W1s[1 * HD + lane], h);
    h = fmaf(acc.z, W1s[2 * HD + lane], h);
    h = fmaf(acc.w, W1s[3 * HD + lane], h);
    h = fmaxf(h, 0.f);

    // o[lane] = sum_k h_k * W2[k][lane]
    float o = 0.f;
#pragma unroll
    for (int k = 0; k < HD; k++) {
        float hk = __shfl_sync(0xffffffffu, h, k);
        o = fmaf(hk, W2s[k * HD + lane], o);
    }
    g_Bh[(size_t)i * HD + lane] = __float2half_rn(dv * o);   // prescaled store
}

// fp16 gather: warp = 4 edge-groups x 8 lanes; returns (sum_e ew*src[e] + src[i]),
// replicated across groups. Caller applies dinv and bias.
__device__ __forceinline__ float4 gather_node_h(const uint2* __restrict__ src, int i,
                                                int grp, int sub) {
    int beg = g_off[i];
    int cnt = g_cnt[i];
    float4 acc  = make_float4(0.f, 0.f, 0.f, 0.f);
    float4 acc2 = make_float4(0.f, 0.f, 0.f, 0.f);
    int e = 0;
#pragma unroll 2
    for (; e + 8 <= cnt; e += 8) {               // two independent chains per lane
        int2 ce0 = g_csr[beg + e + grp];
        int2 ce1 = g_csr[beg + e + 4 + grp];
        float w0 = __int_as_float(ce0.y);
        float w1 = __int_as_float(ce1.y);
        uint2 u0 = src[(size_t)ce0.x * 8 + sub];
        uint2 u1 = src[(size_t)ce1.x * 8 + sub];
        float2 a01 = __half22float2(*reinterpret_cast<__half2*>(&u0.x));
        float2 a23 = __half22float2(*reinterpret_cast<__half2*>(&u0.y));
        float2 b01 = __half22float2(*reinterpret_cast<__half2*>(&u1.x));
        float2 b23 = __half22float2(*reinterpret_cast<__half2*>(&u1.y));
        acc.x  = fmaf(w0, a01.x, acc.x);  acc.y  = fmaf(w0, a01.y, acc.y);
        acc.z  = fmaf(w0, a23.x, acc.z);  acc.w  = fmaf(w0, a23.y, acc.w);
        acc2.x = fmaf(w1, b01.x, acc2.x); acc2.y = fmaf(w1, b01.y, acc2.y);
        acc2.z = fmaf(w1, b23.x, acc2.z); acc2.w = fmaf(w1, b23.y, acc2.w);
    }
    acc.x += acc2.x; acc.y += acc2.y; acc.z += acc2.z; acc.w += acc2.w;
    if (e + 4 <= cnt) {
        int2 ce = g_csr[beg + e + grp];
        float w = __int_as_float(ce.y);
        uint2 u = src[(size_t)ce.x * 8 + sub];
        float2 a01 = __half22float2(*reinterpret_cast<__half2*>(&u.x));
        float2 a23 = __half22float2(*reinterpret_cast<__half2*>(&u.y));
        acc.x = fmaf(w, a01.x, acc.x); acc.y = fmaf(w, a01.y, acc.y);
        acc.z = fmaf(w, a23.x, acc.z); acc.w = fmaf(w, a23.y, acc.w);
        e += 4;
    }
    int rem = cnt - e;
    if (rem > 0) {
        int g2 = min(grp, rem - 1);              // clamp: valid load, zero weight
        int2 ce = g_csr[beg + e + g2];
        float w = (grp < rem) ? __int_as_float(ce.y) : 0.f;
        uint2 u = src[(size_t)ce.x * 8 + sub];
        float2 a01 = __half22float2(*reinterpret_cast<__half2*>(&u.x));
        float2 a23 = __half22float2(*reinterpret_cast<__half2*>(&u.y));
        acc.x = fmaf(w, a01.x, acc.x); acc.y = fmaf(w, a01.y, acc.y);
        acc.z = fmaf(w, a23.x, acc.z); acc.w = fmaf(w, a23.y, acc.w);
    }
#pragma unroll
    for (int d = 8; d <= 16; d <<= 1) {          // reduce across the 4 groups
        acc.x += __shfl_xor_sync(0xffffffffu, acc.x, d);
        acc.y += __shfl_xor_sync(0xffffffffu, acc.y, d);
        acc.z += __shfl_xor_sync(0xffffffffu, acc.z, d);
        acc.w += __shfl_xor_sync(0xffffffffu, acc.w, d);
    }
    uint2 us = src[(size_t)i * 8 + sub];         // self row (already prescaled)
    float2 s01 = __half22float2(*reinterpret_cast<__half2*>(&us.x));
    float2 s23 = __half22float2(*reinterpret_cast<__half2*>(&us.y));
    acc.x += s01.x; acc.y += s01.y; acc.z += s23.x; acc.w += s23.y;
    return acc;
}

// Layer 2: gather g_Bh; v = dv*acc + b2; relu; @W3; store g_Ah = fp16(dv * o).
__global__ void k_layer2(const float* __restrict__ bias, const float* __restrict__ W) {
    __shared__ float4 Ws[HD * 8];                 // W[k][f] as float4: Ws[k*8 + sub]
    int tid = threadIdx.x;
    for (int k = tid; k < HD * 8; k += blockDim.x)
        Ws[k] = reinterpret_cast<const float4*>(W)[k];
    __syncthreads();
    int t = blockIdx.x * blockDim.x + tid;
    int i = t >> 5, lane = t & 31, grp = lane >> 3, sub = lane & 7;
    if (i >= NN) return;

    float4 v = gather_node_h(reinterpret_cast<const uint2*>(g_Bh), i, grp, sub);
    float dv = g_deg[i];
    float4 b4 = __ldg(&reinterpret_cast<const float4*>(bias)[sub]);
    v.x = fmaxf(fmaf(v.x, dv, b4.x), 0.f);
    v.y = fmaxf(fmaf(v.y, dv, b4.y), 0.f);
    v.z = fmaxf(fmaf(v.z, dv, b4.z), 0.f);
    v.w = fmaxf(fmaf(v.w, dv, b4.w), 0.f);

    float4 o = make_float4(0.f, 0.f, 0.f, 0.f);
#pragma unroll
    for (int j = 0; j < 8; j++) {
        int srcLane = grp * 10 + (j >> 2);        // = grp*8 + ((grp*8+j)>>2)
        float comp = ((j & 3) == 0) ? v.x : ((j & 3) == 1) ? v.y
                   : ((j & 3) == 2) ? v.z : v.w;
        float vk = __shfl_sync(0xffffffffu, comp, srcLane);
        float4 w4 = Ws[(grp * 8 + j) * 8 + sub];
        o.x = fmaf(vk, w4.x, o.x); o.y = fmaf(vk, w4.y, o.y);
        o.z = fmaf(vk, w4.z, o.z); o.w = fmaf(vk, w4.w, o.w);
    }
#pragma unroll
    for (int d = 8; d <= 16; d <<= 1) {
        o.x += __shfl_xor_sync(0xffffffffu, o.x, d);
        o.y += __shfl_xor_sync(0xffffffffu, o.y, d);
        o.z += __shfl_xor_sync(0xffffffffu, o.z, d);
        o.w += __shfl_xor_sync(0xffffffffu, o.w, d);
    }
    if (grp == 0) {
        __half2 p0 = __floats2half2_rn(dv * o.x, dv * o.y);
        __half2 p1 = __floats2half2_rn(dv * o.z, dv * o.w);
        uint2 st;
        st.x = *reinterpret_cast<unsigned*>(&p0);
        st.y = *reinterpret_cast<unsigned*>(&p1);
        reinterpret_cast<uint2*>(g_Ah)[(size_t)i * 8 + sub] = st;
    }
}

// Layer 3: gather g_Ah; v = dv*acc + b3; mean-pool (batch sorted: 8 consecutive
// nodes per block -> usually one atomic per feature per block).
__global__ void k_gather_pool(const float* __restrict__ bias,
                              const void* __restrict__ batch) {
    __shared__ float s[8][HD];
    __shared__ int sg[8];
    int tid = threadIdx.x;
    int t = blockIdx.x * blockDim.x + tid;
    int i = t >> 5, lane = t & 31, grp = lane >> 3, sub = lane & 7;
    int warpid = tid >> 5;
    float4 v = gather_node_h(reinterpret_cast<const uint2*>(g_Ah), i, grp, sub);
    float dv = g_deg[i];
    float4 b4 = __ldg(&reinterpret_cast<const float4*>(bias)[sub]);
    v.x = fmaf(v.x, dv, b4.x);
    v.y = fmaf(v.y, dv, b4.y);
    v.z = fmaf(v.z, dv, b4.z);
    v.w = fmaf(v.w, dv, b4.w);
    if (grp == 0)
        *reinterpret_cast<float4*>(&s[warpid][sub * 4]) = v;
    if (lane == 0) sg[warpid] = ldidx(batch, i);
    __syncthreads();
    if (tid < HD) {
        int g0 = sg[0];
        if (g0 == sg[7]) {                        // sorted => all 8 equal
            float sum = 0.f;
#pragma unroll
            for (int w = 0; w < 8; w++) sum += s[w][tid];
            atomicAdd(&g_gsum[g0 * HD + tid], sum);
            if (tid == 0) atomicAdd(&g_gcnt[g0], 8.0f);
        } else {
#pragma unroll
            for (int w = 0; w < 8; w++)
                atomicAdd(&g_gsum[sg[w] * HD + tid], s[w][tid]);
            if (tid == 0) {
#pragma unroll
                for (int w = 0; w < 8; w++) atomicAdd(&g_gcnt[sg[w]], 1.0f);
            }
        }
    }
}

// Head: softmax((pooled_mean @ lin_w) + lin_b) per graph.
__global__ void k_head(const float* __restrict__ lw, const float* __restrict__ lb,
                       float* __restrict__ out) {
    int g = blockIdx.x * blockDim.x + threadIdx.x;
    if (g >= NG) return;
    float inv = 1.0f / fmaxf(g_gcnt[g], 1.0f);
    float l0 = __ldg(&lb[0]), l1 = __ldg(&lb[1]), l2 = __ldg(&lb[2]);
#pragma unroll 8
    for (int k = 0; k < HD; k++) {
        float p = g_gsum[g * HD + k] * inv;
        l0 += p * __ldg(&lw[k * 3 + 0]);
        l1 += p * __ldg(&lw[k * 3 + 1]);
        l2 += p * __ldg(&lw[k * 3 + 2]);
    }
    float m = fmaxf(l0, fmaxf(l1, l2));
    float e0 = expf(l0 - m), e1 = expf(l1 - m), e2 = expf(l2 - m);
    float s = 1.0f / (e0 + e1 + e2);
    out[g * 3 + 0] = e0 * s;
    out[g * 3 + 1] = e1 * s;
    out[g * 3 + 2] = e2 * s;
}

extern "C" void kernel_launch(void* const* d_in, const int* in_sizes, int n_in,
                              void* d_out, int out_size) {
    const float* x     = (const float*)d_in[0];
    const void*  ei    = d_in[1];
    const float* ew    = (const float*)d_in[2];
    const void*  batch = d_in[3];
    const float* W1    = (const float*)d_in[4];
    const float* b1    = (const float*)d_in[5];
    const float* W2    = (const float*)d_in[6];
    const float* b2    = (const float*)d_in[7];
    const float* W3    = (const float*)d_in[8];
    const float* b3    = (const float*)d_in[9];
    const float* lw    = (const float*)d_in[10];
    const float* lb    = (const float*)d_in[11];
    float* out = (float*)d_out;

    const int B = 256;
    const int gbN  = (NN + B - 1) / B;
    const int gbE  = (NE + B - 1) / B;
    const int gbNH = (NN * HD) / B;           // exactly 12500 blocks, 8 nodes each

    k_init<<<gbN, B>>>(ei);
    k_hist<<<gbE, B>>>(ei);
    k_scan1<<<NB, SCAN_B>>>();
    k_scan2<<<1, 256>>>();
    k_scan3<<<gbN, B>>>();
    k_fill<<<gbE, B>>>(ei, ew);
    k_prep<<<gbNH, B>>>(x);                   // deg from CSR (atomic-free) + prescale x

    k_layer1<<<gbNH, B>>>(W1, b1, W2);        // gather g_x + @W1+b1,relu,@W2 -> g_Bh
    k_layer2<<<gbNH, B>>>(b2, W3);            // gather g_Bh + relu + @W3 -> g_Ah
    k_gather_pool<<<gbNH, B>>>(b3, batch);    // gather g_Ah + sorted-batch pool
    k_head<<<(NG + B - 1) / B, B>>>(lw, lb, out);
}